// round 2
// baseline (speedup 1.0000x reference)
#include <cuda_runtime.h>
#include <cuda_bf16.h>
#include <math.h>

// Problem constants (from reference): N_CUTS=4e6, DIM=64, N_CLUSTERS=50, N_VARIANTS=2000
#define DIM 64
#define MAX_SEG 100000

// Scratch for raw segment sums: 100000 * 64 floats = 25.6 MB (static: allocation-free rule)
__device__ float g_raw[(size_t)MAX_SEG * DIM];
// indptr dtype flag: 1 = int64, 0 = int32 (detected on device each run)
__device__ int g_is64;

// ---------------------------------------------------------------------------
// Kernel 0: detect indptr dtype. If the buffer is little-endian int64 with
// values < 2^31 (n_cuts = 4e6 << 2^31), every odd 32-bit word is zero.
// If it is int32, odd words are sorted random breakpoints — essentially never
// all zero. Probe the first 64 words (safe inside the int32-sized buffer).
// ---------------------------------------------------------------------------
__global__ void detect_kernel(const int* __restrict__ ip_words)
{
    int all_zero = 1;
    #pragma unroll
    for (int k = 1; k < 128; k += 2)
        if (ip_words[k] != 0) all_zero = 0;
    g_is64 = all_zero;
}

// ---------------------------------------------------------------------------
// Kernel 1: CSR segment sum. One CTA per segment (segments are contiguous row
// ranges because indptr is sorted). 128 threads = 8 rows in flight x 16 float4
// lanes per row. Each iteration reads a contiguous 2 KB block (8 rows) fully
// coalesced. Block-local tree reduction over the 8 row groups.
// ---------------------------------------------------------------------------
__global__ void __launch_bounds__(128) seg_sum_kernel(
    const float4* __restrict__ emb,   // [n_cuts * 16] float4 (row = 16 float4)
    const void* __restrict__ indptr,  // [n_seg + 1] int32 or int64
    float* __restrict__ raw)          // [n_seg * 64]
{
    const int s = blockIdx.x;
    long long r0, r1;
    if (g_is64) {
        const long long* ip = (const long long*)indptr;
        r0 = __ldg(&ip[s]); r1 = __ldg(&ip[s + 1]);
    } else {
        const int* ip = (const int*)indptr;
        r0 = (long long)__ldg(&ip[s]); r1 = (long long)__ldg(&ip[s + 1]);
    }

    const int tid = threadIdx.x;
    const int q = tid & 15;   // float4 index within a row (0..15)
    const int g = tid >> 4;   // row group (0..7)

    float ax = 0.f, ay = 0.f, az = 0.f, aw = 0.f;
    for (long long r = r0 + g; r < r1; r += 8) {
        float4 v = __ldg(&emb[r * 16 + q]);
        ax += v.x; ay += v.y; az += v.z; aw += v.w;
    }

    __shared__ float4 sm[128];
    sm[tid] = make_float4(ax, ay, az, aw);
    __syncthreads();

    #pragma unroll
    for (int st = 64; st >= 16; st >>= 1) {
        if (tid < st) {
            float4 a = sm[tid];
            float4 b = sm[tid + st];
            sm[tid] = make_float4(a.x + b.x, a.y + b.y, a.z + b.z, a.w + b.w);
        }
        __syncthreads();
    }

    if (tid < 16) {
        float4 r = sm[tid];
        float* dst = raw + (long long)s * DIM + tid * 4;
        dst[0] = r.x; dst[1] = r.y; dst[2] = r.z; dst[3] = r.w;
    }
}

// ---------------------------------------------------------------------------
// Kernel 2: per-(variant, dim) normalization across clusters.
//   ve = log1p(raw / lib[c]) - 2
//   mean/std (ddof=1) over the cluster axis; rel = (ve - mean)/(std + 1e-5)
// Statistics are computed on UNSHIFTED y = log1p(raw/lib) to avoid fp32
// catastrophic cancellation from the -2 offset (variance is shift-invariant).
// Two passes over c (recompute) instead of a local array -> no spills.
// ---------------------------------------------------------------------------
__global__ void finalize_kernel(
    const float* __restrict__ raw,   // [n_clusters * n_variants * 64]
    const float* __restrict__ lib,   // [n_clusters]
    float* __restrict__ out,         // [n_clusters * n_variants * 128]
    int n_clusters, int n_variants)
{
    const int idx = blockIdx.x * blockDim.x + threadIdx.x; // v*64 + d
    const int total = n_variants * DIM;
    if (idx >= total) return;

    const int v = idx >> 6;
    const int d = idx & 63;

    const long long base = (long long)v * DIM + d;
    const long long cstride = (long long)n_variants * DIM;

    float sum = 0.f, sumsq = 0.f;
    for (int c = 0; c < n_clusters; ++c) {
        float y = log1pf(__ldg(&raw[base + (long long)c * cstride]) / __ldg(&lib[c]));
        sum += y;
        sumsq += y * y;
    }

    const float invn = 1.f / (float)n_clusters;
    const float meanY = sum * invn;
    const float var = (sumsq - sum * meanY) / (float)(n_clusters - 1);
    const float stdv = sqrtf(fmaxf(var, 0.f));
    const float inv_denom = 1.f / (stdv + 1e-5f);

    for (int c = 0; c < n_clusters; ++c) {
        float y = log1pf(__ldg(&raw[base + (long long)c * cstride]) / __ldg(&lib[c]));
        long long o = ((long long)c * n_variants + v) * (2 * DIM);
        out[o + d] = y - 2.0f;
        out[o + DIM + d] = (y - meanY) * inv_denom;
    }
}

extern "C" void kernel_launch(void* const* d_in, const int* in_sizes, int n_in,
                              void* d_out, int out_size)
{
    const float* emb    = (const float*)d_in[0];   // [n_cuts, 64] fp32
    const float* lib    = (const float*)d_in[1];   // [n_clusters] fp32
    const void*  indptr = d_in[2];                 // [n_seg + 1] int32 OR int64

    const int n_clusters = in_sizes[1];
    const int n_seg      = in_sizes[2] - 1;
    const int n_variants = n_seg / n_clusters;

    float* raw;
    cudaGetSymbolAddress((void**)&raw, g_raw);

    // Kernel 0: dtype detection (1 thread, trivial)
    detect_kernel<<<1, 1>>>((const int*)indptr);

    // Kernel 1: one block per segment
    seg_sum_kernel<<<n_seg, 128>>>((const float4*)emb, indptr, raw);

    // Kernel 2: one thread per (variant, dim)
    const int total = n_variants * DIM;
    const int threads = 256;
    const int blocks = (total + threads - 1) / threads;
    finalize_kernel<<<blocks, threads>>>(raw, lib, (float*)d_out,
                                         n_clusters, n_variants);
}